// round 7
// baseline (speedup 1.0000x reference)
#include <cuda_runtime.h>
#include <cuda_fp16.h>

#define N_NODES 50000
#define OUT_DIM 128
#define NNZ_X 800000
#define N_EDGES 1600000

// ---- persistent scratch (__device__ globals; zero-initialized at load) ----
__device__ __half g_hh[N_NODES * OUT_DIM];           // 12.8 MB intermediate (fp16)
__device__ int   g_xcnt[N_NODES];                     // zero at entry of every call
__device__ int   g_acnt[N_NODES];                     // (self-cleaned by scan)
__device__ int   g_xstart[N_NODES + 1];
__device__ int   g_astart[N_NODES + 1];
__device__ int   g_xcur[N_NODES];
__device__ int   g_acur[N_NODES];
__device__ int2  g_xs[NNZ_X];                         // 6.4 MB  {col, val bits}
__device__ int2  g_as[N_EDGES];                       // 12.8 MB {col, val bits}

// ---- 1: histogram rows (counters zeroed by previous call's scan) ----
__global__ void hist_kernel(const int4* __restrict__ x_rows4,
                            const int4* __restrict__ adj_rows4) {
    int idx = blockIdx.x * blockDim.x + threadIdx.x;
    int stride = gridDim.x * blockDim.x;
    for (int i = idx; i < NNZ_X / 4; i += stride) {
        int4 r = x_rows4[i];
        atomicAdd(&g_xcnt[r.x], 1);
        atomicAdd(&g_xcnt[r.y], 1);
        atomicAdd(&g_xcnt[r.z], 1);
        atomicAdd(&g_xcnt[r.w], 1);
    }
    for (int i = idx; i < N_EDGES / 4; i += stride) {
        int4 r = adj_rows4[i];
        atomicAdd(&g_acnt[r.x], 1);
        atomicAdd(&g_acnt[r.y], 1);
        atomicAdd(&g_acnt[r.z], 1);
        atomicAdd(&g_acnt[r.w], 1);
    }
}

// ---- 2: exclusive scan (warp-shuffle); 2 blocks; self-cleans cnt ----
#define SCAN_T 1024
#define CHUNK 49   // 1024*49 >= 50000

__device__ __forceinline__ void scan_one(int* __restrict__ cnt,
                                         int* __restrict__ start,
                                         int* __restrict__ cur,
                                         int* wsum) {
    int t = threadIdx.x;
    int lane = t & 31, wid = t >> 5;
    int lo = t * CHUNK;
    int hi = min(lo + CHUNK, N_NODES);
    int sum = 0;
    for (int i = lo; i < hi; i++) sum += cnt[i];
    int v = sum;
#pragma unroll
    for (int d = 1; d < 32; d <<= 1) {
        int u = __shfl_up_sync(0xffffffffu, v, d);
        if (lane >= d) v += u;
    }
    if (lane == 31) wsum[wid] = v;
    __syncthreads();
    if (wid == 0) {
        int w = wsum[lane];
#pragma unroll
        for (int d = 1; d < 32; d <<= 1) {
            int u = __shfl_up_sync(0xffffffffu, w, d);
            if (lane >= d) w += u;
        }
        wsum[lane] = w;
    }
    __syncthreads();
    int off = v - sum + (wid > 0 ? wsum[wid - 1] : 0);   // exclusive prefix
    for (int i = lo; i < hi; i++) {
        start[i] = off;
        cur[i] = off;
        off += cnt[i];
        cnt[i] = 0;                                      // self-clean for next replay
    }
    if (t == SCAN_T - 1) start[N_NODES] = off;
}

__global__ void scan_kernel() {
    __shared__ int wsum[32];
    if (blockIdx.x == 0) scan_one(g_xcnt, g_xstart, g_xcur, wsum);
    else                 scan_one(g_acnt, g_astart, g_acur, wsum);
}

// ---- 3: scatter into row-sorted order (x4 vectorized, round-4 shape) ----
__global__ void scatter_kernel(const int4* __restrict__ x_rows4,
                               const int4* __restrict__ x_cols4,
                               const float4* __restrict__ x_vals4,
                               const float4* __restrict__ noise4,
                               const int4* __restrict__ adj_rows4,
                               const int4* __restrict__ adj_cols4,
                               const float4* __restrict__ adj_vals4) {
    int idx = blockIdx.x * blockDim.x + threadIdx.x;
    int stride = gridDim.x * blockDim.x;
    for (int i = idx; i < NNZ_X / 4; i += stride) {
        int4 r = x_rows4[i];
        int4 c = x_cols4[i];
        float4 v = x_vals4[i];
        float4 n = noise4[i];
        v.x *= floorf(1.0f + n.x);   // keep_prob=1 -> mask==1 (faithful to ref)
        v.y *= floorf(1.0f + n.y);
        v.z *= floorf(1.0f + n.z);
        v.w *= floorf(1.0f + n.w);
        g_xs[atomicAdd(&g_xcur[r.x], 1)] = make_int2(c.x, __float_as_int(v.x));
        g_xs[atomicAdd(&g_xcur[r.y], 1)] = make_int2(c.y, __float_as_int(v.y));
        g_xs[atomicAdd(&g_xcur[r.z], 1)] = make_int2(c.z, __float_as_int(v.z));
        g_xs[atomicAdd(&g_xcur[r.w], 1)] = make_int2(c.w, __float_as_int(v.w));
    }
    for (int i = idx; i < N_EDGES / 4; i += stride) {
        int4 r = adj_rows4[i];
        int4 c = adj_cols4[i];
        float4 v = adj_vals4[i];
        g_as[atomicAdd(&g_acur[r.x], 1)] = make_int2(c.x, __float_as_int(v.x));
        g_as[atomicAdd(&g_acur[r.y], 1)] = make_int2(c.y, __float_as_int(v.y));
        g_as[atomicAdd(&g_acur[r.z], 1)] = make_int2(c.z, __float_as_int(v.z));
        g_as[atomicAdd(&g_acur[r.w], 1)] = make_int2(c.w, __float_as_int(v.w));
    }
}

// ---- 4: hop1  h[row] = sum v * W[col]  (warp per row, predicated x4) ----
__global__ void hop1_kernel(const float4* __restrict__ W4) {
    int row = (blockIdx.x * blockDim.x + threadIdx.x) >> 5;
    int lane = threadIdx.x & 31;
    if (row >= N_NODES) return;
    int s0 = g_xstart[row], s1 = g_xstart[row + 1];
    float4 acc = make_float4(0.f, 0.f, 0.f, 0.f);
    for (int i = s0; i < s1; i += 4) {
        int2 e[4];
        float4 w[4];
        float vv[4];
#pragma unroll
        for (int k = 0; k < 4; k++) {
            int j = i + k;
            int jc = j < s1 ? j : s1 - 1;        // clamp within row (s1>s0 here)
            e[k] = g_xs[jc];
            vv[k] = (j < s1) ? __int_as_float(e[k].y) : 0.f;
        }
#pragma unroll
        for (int k = 0; k < 4; k++) w[k] = W4[e[k].x * 32 + lane];
#pragma unroll
        for (int k = 0; k < 4; k++) {
            acc.x += vv[k] * w[k].x;
            acc.y += vv[k] * w[k].y;
            acc.z += vv[k] * w[k].z;
            acc.w += vv[k] * w[k].w;
        }
    }
    __half2 lo = __floats2half2_rn(acc.x, acc.y);
    __half2 hi = __floats2half2_rn(acc.z, acc.w);
    uint2 u;
    u.x = *reinterpret_cast<unsigned*>(&lo);
    u.y = *reinterpret_cast<unsigned*>(&hi);
    reinterpret_cast<uint2*>(g_hh)[row * 32 + lane] = u;
}

// ---- 5: hop2  out[row] = relu(sum w * h_fp16[col])  (warp per row, predicated x8) ----
__device__ __forceinline__ void fma_h(float4& acc, float v, uint2 u) {
    __half2 lo = *reinterpret_cast<__half2*>(&u.x);
    __half2 hi = *reinterpret_cast<__half2*>(&u.y);
    float2 f0 = __half22float2(lo);
    float2 f1 = __half22float2(hi);
    acc.x += v * f0.x; acc.y += v * f0.y;
    acc.z += v * f1.x; acc.w += v * f1.y;
}

__global__ void hop2_kernel(float4* __restrict__ out4) {
    int row = (blockIdx.x * blockDim.x + threadIdx.x) >> 5;
    int lane = threadIdx.x & 31;
    if (row >= N_NODES) return;
    int s0 = g_astart[row], s1 = g_astart[row + 1];
    const uint2* __restrict__ h2 = reinterpret_cast<const uint2*>(g_hh);
    float4 acc = make_float4(0.f, 0.f, 0.f, 0.f);
    for (int i = s0; i < s1; i += 8) {
        int2 e[8];
        uint2 u[8];
        float vv[8];
#pragma unroll
        for (int k = 0; k < 8; k++) {
            int j = i + k;
            int jc = j < s1 ? j : s1 - 1;        // clamp within row
            e[k] = g_as[jc];
            vv[k] = (j < s1) ? __int_as_float(e[k].y) : 0.f;
        }
#pragma unroll
        for (int k = 0; k < 8; k++) u[k] = h2[e[k].x * 32 + lane];
#pragma unroll
        for (int k = 0; k < 8; k++) fma_h(acc, vv[k], u[k]);
    }
    acc.x = fmaxf(acc.x, 0.f); acc.y = fmaxf(acc.y, 0.f);
    acc.z = fmaxf(acc.z, 0.f); acc.w = fmaxf(acc.w, 0.f);
    out4[row * 32 + lane] = acc;
}

extern "C" void kernel_launch(void* const* d_in, const int* in_sizes, int n_in,
                              void* d_out, int out_size) {
    const int*   x_rows   = (const int*)d_in[0];
    const int*   x_cols   = (const int*)d_in[1];
    const float* x_vals   = (const float*)d_in[2];
    const float* noise    = (const float*)d_in[3];
    const int*   adj_rows = (const int*)d_in[4];
    const int*   adj_cols = (const int*)d_in[5];
    const float* adj_vals = (const float*)d_in[6];
    const float* W        = (const float*)d_in[7];
    float4* out4 = (float4*)d_out;

    hist_kernel<<<1184, 256>>>((const int4*)x_rows, (const int4*)adj_rows);
    scan_kernel<<<2, SCAN_T>>>();
    scatter_kernel<<<1184, 256>>>((const int4*)x_rows, (const int4*)x_cols,
                                  (const float4*)x_vals, (const float4*)noise,
                                  (const int4*)adj_rows, (const int4*)adj_cols,
                                  (const float4*)adj_vals);

    hop1_kernel<<<(N_NODES * 32 + 255) / 256, 256>>>(reinterpret_cast<const float4*>(W));
    hop2_kernel<<<(N_NODES * 32 + 255) / 256, 256>>>(out4);
}